// round 1
// baseline (speedup 1.0000x reference)
#include <cuda_runtime.h>
#include <cuda_bf16.h>

// Problem constants (fixed by setup_inputs)
#define NUM_NEW 50000
#define D_MODEL 3584
#define D_ENC   128
#define NB      2048      // batch / segments
#define SEG     32        // tokens per segment
#define CHUNK   512       // floats of D_MODEL per gather block (3584 = 7 * 512)

// Scratch for segment means: [NB, D_MODEL] fp32 = 29.4 MB (static device array: allowed)
__device__ float g_means[(size_t)NB * D_MODEL];

// ---------------------------------------------------------------------------
// Kernel 1: fused embedding gather + segment sum + mean.
// grid = (7, 2048), block = 128 threads. Each block owns (segment b, 512-dim chunk).
// Each thread accumulates a float4 (4 dims) over the 32 tokens of the segment.
// ---------------------------------------------------------------------------
__global__ __launch_bounds__(128) void gather_mean_kernel(
    const int* __restrict__ flat_idx,
    const int* __restrict__ lens,
    const float* __restrict__ embed)
{
    __shared__ int idx_s[SEG];
    const int b     = blockIdx.y;
    const int chunk = blockIdx.x;
    const int tid   = threadIdx.x;

    if (tid < SEG) idx_s[tid] = flat_idx[b * SEG + tid];
    __syncthreads();

    const int d = chunk * CHUNK + tid * 4;

    float4 acc = make_float4(0.f, 0.f, 0.f, 0.f);
    #pragma unroll
    for (int t = 0; t < SEG; t++) {
        const float4 v = __ldg(reinterpret_cast<const float4*>(
            embed + (size_t)idx_s[t] * D_MODEL + d));
        acc.x += v.x; acc.y += v.y; acc.z += v.z; acc.w += v.w;
    }

    const float inv = 1.0f / (float)lens[b];
    acc.x *= inv; acc.y *= inv; acc.z *= inv; acc.w *= inv;

    *reinterpret_cast<float4*>(g_means + (size_t)b * D_MODEL + d) = acc;
}

// ---------------------------------------------------------------------------
// Kernel 2: initialize output with bias (output then accumulated via atomics).
// out: [NB, D_ENC] fp32, 262144 elements.
// ---------------------------------------------------------------------------
__global__ __launch_bounds__(256) void init_out_kernel(
    const float* __restrict__ bias,
    float* __restrict__ out)
{
    const int i = blockIdx.x * blockDim.x + threadIdx.x;
    if (i < NB * D_ENC) out[i] = bias[i & (D_ENC - 1)];
}

// ---------------------------------------------------------------------------
// Kernel 3: split-K GEMM  out += means @ W
//   means: [NB, D_MODEL], W: [D_MODEL, D_ENC]
// grid = (NB/128 = 16, D_MODEL/128 = 28), block = 256 threads.
// Each block: M-tile 128 x N 128 over a 128-deep K chunk; 8x8 register tile
// per thread; atomicAdd partials into out.
// ---------------------------------------------------------------------------
#define TM 128
#define TN 128
#define KT 16
#define KC 128

__global__ __launch_bounds__(256) void gemm_splitk_kernel(
    const float* __restrict__ W,
    float* __restrict__ out)
{
    __shared__ float As[KT][TM + 4];  // k-major, padded (stride 132, /4 aligned)
    __shared__ float Bs[KT][TN];      // k-major

    const int m0  = blockIdx.x * TM;
    const int k0  = blockIdx.y * KC;
    const int tid = threadIdx.x;
    const int tx  = tid & 15;        // 0..15 -> n block of 8
    const int ty  = tid >> 4;        // 0..15 -> m block of 8

    float acc[8][8];
    #pragma unroll
    for (int i = 0; i < 8; i++)
        #pragma unroll
        for (int j = 0; j < 8; j++) acc[i][j] = 0.f;

    for (int kc = 0; kc < KC; kc += KT) {
        const int kbase = k0 + kc;

        // Load A tile [TM x KT] transposed into As[k][m]
        {
            const int c  = tid & 15;   // k within tile
            const int r0 = tid >> 4;   // row group
            #pragma unroll
            for (int i = 0; i < 8; i++) {
                const int m = r0 + i * 16;
                As[c][m] = g_means[(size_t)(m0 + m) * D_MODEL + kbase + c];
            }
        }
        // Load B tile [KT x TN] into Bs[k][n]
        {
            const int n   = tid & 127;
            const int kk0 = tid >> 7;  // 0..1
            #pragma unroll
            for (int i = 0; i < 8; i++) {
                const int kk = kk0 + i * 2;
                Bs[kk][n] = W[(size_t)(kbase + kk) * D_ENC + n];
            }
        }
        __syncthreads();

        #pragma unroll
        for (int k = 0; k < KT; k++) {
            float a[8], bb[8];
            const float4 a0 = *reinterpret_cast<const float4*>(&As[k][ty * 8]);
            const float4 a1 = *reinterpret_cast<const float4*>(&As[k][ty * 8 + 4]);
            const float4 b0 = *reinterpret_cast<const float4*>(&Bs[k][tx * 8]);
            const float4 b1 = *reinterpret_cast<const float4*>(&Bs[k][tx * 8 + 4]);
            a[0]=a0.x; a[1]=a0.y; a[2]=a0.z; a[3]=a0.w;
            a[4]=a1.x; a[5]=a1.y; a[6]=a1.z; a[7]=a1.w;
            bb[0]=b0.x; bb[1]=b0.y; bb[2]=b0.z; bb[3]=b0.w;
            bb[4]=b1.x; bb[5]=b1.y; bb[6]=b1.z; bb[7]=b1.w;
            #pragma unroll
            for (int i = 0; i < 8; i++)
                #pragma unroll
                for (int j = 0; j < 8; j++)
                    acc[i][j] = fmaf(a[i], bb[j], acc[i][j]);
        }
        __syncthreads();
    }

    // Accumulate partials
    #pragma unroll
    for (int i = 0; i < 8; i++) {
        const int m = m0 + ty * 8 + i;
        #pragma unroll
        for (int j = 0; j < 8; j++) {
            atomicAdd(&out[(size_t)m * D_ENC + tx * 8 + j], acc[i][j]);
        }
    }
}

// ---------------------------------------------------------------------------
// Launch
// Inputs (metadata order):
//   0: flat_idx int32 [65536]
//   1: seg      int32 [65536]   (implied layout: SEG consecutive tokens/segment)
//   2: lens     int32 [2048]
//   3: embed_weight f32 [50000*3584]
//   4: proj_w   f32 [3584*128]
//   5: proj_b   f32 [128]
// Output: f32 [2048*128]
// ---------------------------------------------------------------------------
extern "C" void kernel_launch(void* const* d_in, const int* in_sizes, int n_in,
                              void* d_out, int out_size)
{
    const int*   flat_idx = (const int*)d_in[0];
    const int*   lens     = (const int*)d_in[2];
    const float* embed    = (const float*)d_in[3];
    const float* proj_w   = (const float*)d_in[4];
    const float* proj_b   = (const float*)d_in[5];
    float*       out      = (float*)d_out;

    // 1) output = bias broadcast
    init_out_kernel<<<(NB * D_ENC + 255) / 256, 256>>>(proj_b, out);

    // 2) means = segment-mean of gathered embeddings
    gather_mean_kernel<<<dim3(D_MODEL / CHUNK, NB), 128>>>(flat_idx, lens, embed);

    // 3) out += means @ W (split-K, atomic accumulate)
    gemm_splitk_kernel<<<dim3(NB / TM, D_MODEL / KC), 256>>>(proj_w, out);
}

// round 5
// speedup vs baseline: 1.1030x; 1.1030x over previous
#include <cuda_runtime.h>
#include <cuda_bf16.h>
#include <cstdint>

// Problem constants (fixed by setup_inputs)
#define NUM_NEW 50000
#define D_MODEL 3584
#define D_ENC   128
#define NB      2048      // batch / segments
#define SEG     32        // tokens per segment
#define CHUNK   512       // floats of D_MODEL per gather block (3584 = 7 * 512)

// Scratch for segment means: [NB, D_MODEL] fp32 = 29.4 MB
__device__ float g_means[(size_t)NB * D_MODEL];

// ---------------------------------------------------------------------------
// Kernel 1: fused embedding gather + segment sum + mean. (HBM-bound, ~145us)
// grid = (7, 2048), block = 128. Each block owns (segment b, 512-dim chunk).
// ---------------------------------------------------------------------------
__global__ __launch_bounds__(128) void gather_mean_kernel(
    const int* __restrict__ flat_idx,
    const int* __restrict__ lens,
    const float* __restrict__ embed)
{
    __shared__ int idx_s[SEG];
    const int b     = blockIdx.y;
    const int chunk = blockIdx.x;
    const int tid   = threadIdx.x;

    if (tid < SEG) idx_s[tid] = flat_idx[b * SEG + tid];
    __syncthreads();

    const int d = chunk * CHUNK + tid * 4;

    float4 acc = make_float4(0.f, 0.f, 0.f, 0.f);
    #pragma unroll
    for (int t = 0; t < SEG; t++) {
        const float4 v = __ldg(reinterpret_cast<const float4*>(
            embed + (size_t)idx_s[t] * D_MODEL + d));
        acc.x += v.x; acc.y += v.y; acc.z += v.z; acc.w += v.w;
    }

    const float inv = 1.0f / (float)lens[b];
    acc.x *= inv; acc.y *= inv; acc.z *= inv; acc.w *= inv;

    *reinterpret_cast<float4*>(g_means + (size_t)b * D_MODEL + d) = acc;
}

// ---------------------------------------------------------------------------
// Kernel 2: split-K tensor-core GEMM  out += means @ W  (+ bias from ky==0)
// tf32 mma.sync with hi/lo split for ~fp32 accuracy.
//   means: [NB, D_MODEL], W: [D_MODEL, D_ENC], out: [NB, D_ENC]
// grid = (NB/128 = 16, D_MODEL/128 = 28), block = 256 (8 warps).
// Warp grid 4(m) x 2(n): warp tile 32M x 64N. Per warp: 2 m16-tiles x 8 n8-tiles.
// ---------------------------------------------------------------------------
#define KC  128   // K-chunk per CTA
#define KS  16    // K per smem stage
#define AST 20    // As row stride: frag bank = (20*lq+ls)%32 -> 32 distinct, conflict-free
#define BST 132   // Bs row stride: full 128-wide tile + pad (BUG FIX: was 40 -> OOB smem write)

__device__ __forceinline__ float tf32_rna(float x) {
    uint32_t u;
    asm("cvt.rna.tf32.f32 %0, %1;" : "=r"(u) : "f"(x));
    return __uint_as_float(u);
}

__device__ __forceinline__ void mma8(float* d, const uint32_t* a, const uint32_t* b) {
    asm volatile(
        "mma.sync.aligned.m16n8k8.row.col.f32.tf32.tf32.f32 "
        "{%0,%1,%2,%3}, {%4,%5,%6,%7}, {%8,%9}, {%0,%1,%2,%3};\n"
        : "+f"(d[0]), "+f"(d[1]), "+f"(d[2]), "+f"(d[3])
        : "r"(a[0]), "r"(a[1]), "r"(a[2]), "r"(a[3]), "r"(b[0]), "r"(b[1]));
}

__global__ __launch_bounds__(256) void gemm_tf32_kernel(
    const float* __restrict__ W,
    const float* __restrict__ bias,
    float* __restrict__ out)
{
    __shared__ float Ah[128][AST];
    __shared__ float Al[128][AST];
    __shared__ float Bh[KS][BST];
    __shared__ float Bl[KS][BST];

    const int m0   = blockIdx.x * 128;
    const int k0   = blockIdx.y * KC;
    const int t    = threadIdx.x;
    const int w    = t >> 5;
    const int lane = t & 31;
    const int wm   = (w & 3) * 32;   // warp m offset within tile
    const int wn   = (w >> 2) * 64;  // warp n offset
    const int lq   = lane >> 2;      // 0..7
    const int ls   = lane & 3;       // 0..3

    float acc[2][8][4];
    #pragma unroll
    for (int mt = 0; mt < 2; mt++)
        #pragma unroll
        for (int nt = 0; nt < 8; nt++)
            #pragma unroll
            for (int r = 0; r < 4; r++) acc[mt][nt][r] = 0.f;

    for (int ks = 0; ks < KC; ks += KS) {
        const int kb = k0 + ks;

        // Stage A: 128 rows x KS cols, split into hi/lo tf32
        {
            const int r     = t >> 1;       // 0..127
            const int cbase = (t & 1) * 8;  // 0 or 8
            #pragma unroll
            for (int i = 0; i < 2; i++) {
                const int c = cbase + i * 4;  // covers 0..15
                const float4 v = *reinterpret_cast<const float4*>(
                    &g_means[(size_t)(m0 + r) * D_MODEL + kb + c]);
                float4 h, l;
                h.x = tf32_rna(v.x); l.x = tf32_rna(v.x - h.x);
                h.y = tf32_rna(v.y); l.y = tf32_rna(v.y - h.y);
                h.z = tf32_rna(v.z); l.z = tf32_rna(v.z - h.z);
                h.w = tf32_rna(v.w); l.w = tf32_rna(v.w - h.w);
                *reinterpret_cast<float4*>(&Ah[r][c]) = h;
                *reinterpret_cast<float4*>(&Al[r][c]) = l;
            }
        }
        // Stage B: KS rows x 128 cols, split into hi/lo tf32
        {
            #pragma unroll
            for (int i = 0; i < 2; i++) {
                const int f = t + 256 * i;
                const int r = f >> 5;         // 0..15
                const int c = (f & 31) * 4;   // 0..124
                const float4 v = *reinterpret_cast<const float4*>(
                    &W[(size_t)(kb + r) * D_ENC + c]);
                float4 h, l;
                h.x = tf32_rna(v.x); l.x = tf32_rna(v.x - h.x);
                h.y = tf32_rna(v.y); l.y = tf32_rna(v.y - h.y);
                h.z = tf32_rna(v.z); l.z = tf32_rna(v.z - h.z);
                h.w = tf32_rna(v.w); l.w = tf32_rna(v.w - h.w);
                *reinterpret_cast<float4*>(&Bh[r][c]) = h;
                *reinterpret_cast<float4*>(&Bl[r][c]) = l;
            }
        }
        __syncthreads();

        #pragma unroll
        for (int k8 = 0; k8 < KS; k8 += 8) {
            // A fragments for this warp's 2 m16-tiles (hi and lo terms)
            uint32_t afh[2][4], afl[2][4];
            #pragma unroll
            for (int mt = 0; mt < 2; mt++) {
                const int rb = wm + mt * 16;
                afh[mt][0] = __float_as_uint(Ah[rb + lq    ][k8 + ls    ]);
                afh[mt][1] = __float_as_uint(Ah[rb + lq + 8][k8 + ls    ]);
                afh[mt][2] = __float_as_uint(Ah[rb + lq    ][k8 + ls + 4]);
                afh[mt][3] = __float_as_uint(Ah[rb + lq + 8][k8 + ls + 4]);
                afl[mt][0] = __float_as_uint(Al[rb + lq    ][k8 + ls    ]);
                afl[mt][1] = __float_as_uint(Al[rb + lq + 8][k8 + ls    ]);
                afl[mt][2] = __float_as_uint(Al[rb + lq    ][k8 + ls + 4]);
                afl[mt][3] = __float_as_uint(Al[rb + lq + 8][k8 + ls + 4]);
            }
            #pragma unroll
            for (int nt = 0; nt < 8; nt++) {
                const int nb = wn + nt * 8;
                uint32_t bh[2], bl[2];
                bh[0] = __float_as_uint(Bh[k8 + ls    ][nb + lq]);
                bh[1] = __float_as_uint(Bh[k8 + ls + 4][nb + lq]);
                bl[0] = __float_as_uint(Bl[k8 + ls    ][nb + lq]);
                bl[1] = __float_as_uint(Bl[k8 + ls + 4][nb + lq]);
                #pragma unroll
                for (int mt = 0; mt < 2; mt++) {
                    mma8(acc[mt][nt], afh[mt], bh);  // hi*hi
                    mma8(acc[mt][nt], afh[mt], bl);  // hi*lo
                    mma8(acc[mt][nt], afl[mt], bh);  // lo*hi  (lo*lo dropped ~2^-22)
                }
            }
        }
        __syncthreads();
    }

    // Epilogue: bias (only from the ky==0 chunk) + atomic accumulate
    const bool add_bias = (blockIdx.y == 0);
    #pragma unroll
    for (int mt = 0; mt < 2; mt++) {
        const int m = m0 + wm + mt * 16 + lq;
        #pragma unroll
        for (int nt = 0; nt < 8; nt++) {
            const int n = wn + nt * 8 + ls * 2;
            float v0 = acc[mt][nt][0], v1 = acc[mt][nt][1];
            float v2 = acc[mt][nt][2], v3 = acc[mt][nt][3];
            if (add_bias) {
                const float b0 = bias[n], b1 = bias[n + 1];
                v0 += b0; v1 += b1; v2 += b0; v3 += b1;
            }
            atomicAdd(&out[(size_t)m * D_ENC + n],           v0);
            atomicAdd(&out[(size_t)m * D_ENC + n + 1],       v1);
            atomicAdd(&out[(size_t)(m + 8) * D_ENC + n],     v2);
            atomicAdd(&out[(size_t)(m + 8) * D_ENC + n + 1], v3);
        }
    }
}

// ---------------------------------------------------------------------------
// Launch.  Inputs (metadata order):
//   0: flat_idx int32 [65536]   1: seg int32 [65536]   2: lens int32 [2048]
//   3: embed_weight f32 [50000*3584]  4: proj_w f32 [3584*128]  5: proj_b f32 [128]
// Output: f32 [2048*128]
// ---------------------------------------------------------------------------
extern "C" void kernel_launch(void* const* d_in, const int* in_sizes, int n_in,
                              void* d_out, int out_size)
{
    const int*   flat_idx = (const int*)d_in[0];
    const int*   lens     = (const int*)d_in[2];
    const float* embed    = (const float*)d_in[3];
    const float* proj_w   = (const float*)d_in[4];
    const float* proj_b   = (const float*)d_in[5];
    float*       out      = (float*)d_out;

    // 1) zero output (bias added by ky==0 GEMM chunk)
    cudaMemsetAsync(out, 0, (size_t)NB * D_ENC * sizeof(float));

    // 2) means = segment-mean of gathered embeddings
    gather_mean_kernel<<<dim3(D_MODEL / CHUNK, NB), 128>>>(flat_idx, lens, embed);

    // 3) out += means @ W + bias (split-K tf32 tensor cores, atomic accumulate)
    gemm_tf32_kernel<<<dim3(NB / 128, D_MODEL / KC), 256>>>(proj_w, proj_b, out);
}

// round 6
// speedup vs baseline: 1.1601x; 1.0518x over previous
#include <cuda_runtime.h>
#include <cuda_bf16.h>
#include <cstdint>

// Problem constants (fixed by setup_inputs)
#define NUM_NEW 50000
#define D_MODEL 3584
#define D_ENC   128
#define NB      2048      // batch / segments
#define SEG     32        // tokens per segment
#define CHUNK   512       // floats of D_MODEL per gather block (3584 = 7 * 512)

// Scratch for segment means: [NB, D_MODEL] fp32 = 29.4 MB
__device__ float g_means[(size_t)NB * D_MODEL];

// ---------------------------------------------------------------------------
// Kernel 1: fused embedding gather + segment sum + mean. (HBM roofline ~125us)
// ---------------------------------------------------------------------------
__global__ __launch_bounds__(128) void gather_mean_kernel(
    const int* __restrict__ flat_idx,
    const int* __restrict__ lens,
    const float* __restrict__ embed)
{
    __shared__ int idx_s[SEG];
    const int b     = blockIdx.y;
    const int chunk = blockIdx.x;
    const int tid   = threadIdx.x;

    if (tid < SEG) idx_s[tid] = flat_idx[b * SEG + tid];
    __syncthreads();

    const int d = chunk * CHUNK + tid * 4;

    float4 acc = make_float4(0.f, 0.f, 0.f, 0.f);
    #pragma unroll
    for (int t = 0; t < SEG; t++) {
        const float4 v = __ldg(reinterpret_cast<const float4*>(
            embed + (size_t)idx_s[t] * D_MODEL + d));
        acc.x += v.x; acc.y += v.y; acc.z += v.z; acc.w += v.w;
    }

    const float inv = 1.0f / (float)lens[b];
    acc.x *= inv; acc.y *= inv; acc.z *= inv; acc.w *= inv;

    *reinterpret_cast<float4*>(g_means + (size_t)b * D_MODEL + d) = acc;
}

// ---------------------------------------------------------------------------
// Kernel 2: split-K bf16x3 tensor-core GEMM  out += means @ W (+bias on ky==0)
// A = Ah + Al (bf16 pair), B = Bh + Bl; D = Ah*Bh + Ah*Bl + Al*Bh (fp32 acc).
// grid = (16, 28), block = 256 (8 warps: 4m x 2n). Warp tile 32M x 64N.
// Stage = k16 slice; smem holds packed bf16x2 words, row stride 12 words
// (bank = (12*lq+ls)%32 -> all 32 banks, conflict-free fragment LDS).
// ---------------------------------------------------------------------------
#define KC 128   // K chunk per CTA (split-K over 28 chunks)
#define AW 12    // uint32 words per smem row (8 used + 4 pad)

__device__ __forceinline__ void split2(float x, float y, uint32_t& h, uint32_t& l) {
    __nv_bfloat16 hx = __float2bfloat16(x);
    __nv_bfloat16 hy = __float2bfloat16(y);
    __nv_bfloat16 lx = __float2bfloat16(x - __bfloat162float(hx));
    __nv_bfloat16 ly = __float2bfloat16(y - __bfloat162float(hy));
    h = ((uint32_t)__bfloat16_as_ushort(hy) << 16) | __bfloat16_as_ushort(hx);
    l = ((uint32_t)__bfloat16_as_ushort(ly) << 16) | __bfloat16_as_ushort(lx);
}

__device__ __forceinline__ void mma16(float* d, const uint32_t* a, const uint32_t* b) {
    asm volatile(
        "mma.sync.aligned.m16n8k16.row.col.f32.bf16.bf16.f32 "
        "{%0,%1,%2,%3}, {%4,%5,%6,%7}, {%8,%9}, {%0,%1,%2,%3};\n"
        : "+f"(d[0]), "+f"(d[1]), "+f"(d[2]), "+f"(d[3])
        : "r"(a[0]), "r"(a[1]), "r"(a[2]), "r"(a[3]), "r"(b[0]), "r"(b[1]));
}

__global__ __launch_bounds__(256, 2) void gemm_bf16x3_kernel(
    const float* __restrict__ W,
    const float* __restrict__ bias,
    float* __restrict__ out)
{
    __shared__ uint32_t Ah[128][AW], Al[128][AW];  // [m][k-word]
    __shared__ uint32_t Bh[128][AW], Bl[128][AW];  // [n][k-word]

    const int m0   = blockIdx.x * 128;
    const int k0   = blockIdx.y * KC;
    const int t    = threadIdx.x;
    const int w    = t >> 5;
    const int lane = t & 31;
    const int wm   = (w & 3) * 32;   // warp m offset
    const int wn   = (w >> 2) * 64;  // warp n offset
    const int lq   = lane >> 2;      // 0..7
    const int ls   = lane & 3;       // 0..3

    // staging indices
    const int ar = t >> 1;            // A row 0..127
    const int ac = (t & 1) * 8;       // A k base 0 / 8
    const int bn = t & 127;           // B n 0..127
    const int bk = (t >> 7) * 8;      // B k base 0 / 8

    float acc[2][8][4];
    #pragma unroll
    for (int mt = 0; mt < 2; mt++)
        #pragma unroll
        for (int nt = 0; nt < 8; nt++)
            #pragma unroll
            for (int r = 0; r < 4; r++) acc[mt][nt][r] = 0.f;

    float fa[8], fb[8];
    // load stage 0 globals
    {
        const float4 v0 = *reinterpret_cast<const float4*>(&g_means[(size_t)(m0 + ar) * D_MODEL + k0 + ac]);
        const float4 v1 = *reinterpret_cast<const float4*>(&g_means[(size_t)(m0 + ar) * D_MODEL + k0 + ac + 4]);
        fa[0]=v0.x; fa[1]=v0.y; fa[2]=v0.z; fa[3]=v0.w;
        fa[4]=v1.x; fa[5]=v1.y; fa[6]=v1.z; fa[7]=v1.w;
        #pragma unroll
        for (int kk = 0; kk < 8; kk++)
            fb[kk] = W[(size_t)(k0 + bk + kk) * D_ENC + bn];
    }

    #pragma unroll 1
    for (int s = 0; s < KC / 16; s++) {
        // convert + store current stage to smem
        #pragma unroll
        for (int j = 0; j < 4; j++) {
            uint32_t h, l;
            split2(fa[2*j], fa[2*j+1], h, l);
            Ah[ar][(ac >> 1) + j] = h;  Al[ar][(ac >> 1) + j] = l;
            split2(fb[2*j], fb[2*j+1], h, l);
            Bh[bn][(bk >> 1) + j] = h;  Bl[bn][(bk >> 1) + j] = l;
        }
        __syncthreads();

        // prefetch next stage globals (overlaps with mma below)
        if (s + 1 < KC / 16) {
            const int kb = k0 + (s + 1) * 16;
            const float4 v0 = *reinterpret_cast<const float4*>(&g_means[(size_t)(m0 + ar) * D_MODEL + kb + ac]);
            const float4 v1 = *reinterpret_cast<const float4*>(&g_means[(size_t)(m0 + ar) * D_MODEL + kb + ac + 4]);
            fa[0]=v0.x; fa[1]=v0.y; fa[2]=v0.z; fa[3]=v0.w;
            fa[4]=v1.x; fa[5]=v1.y; fa[6]=v1.z; fa[7]=v1.w;
            #pragma unroll
            for (int kk = 0; kk < 8; kk++)
                fb[kk] = W[(size_t)(kb + bk + kk) * D_ENC + bn];
        }

        // compute one k16 step: 2 m-tiles x 8 n-tiles x 3 terms
        uint32_t afh[2][4], afl[2][4];
        #pragma unroll
        for (int mt = 0; mt < 2; mt++) {
            const int rb = wm + mt * 16;
            afh[mt][0] = Ah[rb + lq    ][ls    ];
            afh[mt][1] = Ah[rb + lq + 8][ls    ];
            afh[mt][2] = Ah[rb + lq    ][ls + 4];
            afh[mt][3] = Ah[rb + lq + 8][ls + 4];
            afl[mt][0] = Al[rb + lq    ][ls    ];
            afl[mt][1] = Al[rb + lq + 8][ls    ];
            afl[mt][2] = Al[rb + lq    ][ls + 4];
            afl[mt][3] = Al[rb + lq + 8][ls + 4];
        }
        #pragma unroll
        for (int nt = 0; nt < 8; nt++) {
            const int nb = wn + nt * 8;
            uint32_t bh[2], bl[2];
            bh[0] = Bh[nb + lq][ls];
            bh[1] = Bh[nb + lq][ls + 4];
            bl[0] = Bl[nb + lq][ls];
            bl[1] = Bl[nb + lq][ls + 4];
            #pragma unroll
            for (int mt = 0; mt < 2; mt++) {
                mma16(acc[mt][nt], afh[mt], bh);  // hi*hi
                mma16(acc[mt][nt], afh[mt], bl);  // hi*lo
                mma16(acc[mt][nt], afl[mt], bh);  // lo*hi (lo*lo ~2^-34: dropped)
            }
        }
        __syncthreads();
    }

    // Epilogue: bias (ky==0 only) + atomic accumulate
    const bool add_bias = (blockIdx.y == 0);
    #pragma unroll
    for (int mt = 0; mt < 2; mt++) {
        const int m = m0 + wm + mt * 16 + lq;
        #pragma unroll
        for (int nt = 0; nt < 8; nt++) {
            const int n = wn + nt * 8 + ls * 2;
            float v0 = acc[mt][nt][0], v1 = acc[mt][nt][1];
            float v2 = acc[mt][nt][2], v3 = acc[mt][nt][3];
            if (add_bias) {
                const float b0 = bias[n], b1 = bias[n + 1];
                v0 += b0; v1 += b1; v2 += b0; v3 += b1;
            }
            atomicAdd(&out[(size_t)m * D_ENC + n],           v0);
            atomicAdd(&out[(size_t)m * D_ENC + n + 1],       v1);
            atomicAdd(&out[(size_t)(m + 8) * D_ENC + n],     v2);
            atomicAdd(&out[(size_t)(m + 8) * D_ENC + n + 1], v3);
        }
    }
}

// ---------------------------------------------------------------------------
// Launch.  Inputs (metadata order):
//   0: flat_idx int32 [65536]   1: seg int32 [65536]   2: lens int32 [2048]
//   3: embed_weight f32 [50000*3584]  4: proj_w f32 [3584*128]  5: proj_b f32 [128]
// Output: f32 [2048*128]
// ---------------------------------------------------------------------------
extern "C" void kernel_launch(void* const* d_in, const int* in_sizes, int n_in,
                              void* d_out, int out_size)
{
    const int*   flat_idx = (const int*)d_in[0];
    const int*   lens     = (const int*)d_in[2];
    const float* embed    = (const float*)d_in[3];
    const float* proj_w   = (const float*)d_in[4];
    const float* proj_b   = (const float*)d_in[5];
    float*       out      = (float*)d_out;

    // 1) zero output (bias added by ky==0 GEMM chunk)
    cudaMemsetAsync(out, 0, (size_t)NB * D_ENC * sizeof(float));

    // 2) means = segment-mean of gathered embeddings
    gather_mean_kernel<<<dim3(D_MODEL / CHUNK, NB), 128>>>(flat_idx, lens, embed);

    // 3) out += means @ W + bias (split-K bf16x3 tensor cores)
    gemm_bf16x3_kernel<<<dim3(NB / 128, D_MODEL / KC), 256>>>(proj_w, proj_b, out);
}

// round 7
// speedup vs baseline: 1.3733x; 1.1838x over previous
#include <cuda_runtime.h>
#include <cuda_bf16.h>
#include <cstdint>

// Problem constants (fixed by setup_inputs)
#define NUM_NEW 50000
#define D_MODEL 3584
#define D_ENC   128
#define NB      2048      // batch / segments
#define SEG     32        // tokens per segment
#define CDIM    64        // dims per chunk pass (D_MODEL = 56 * 64)
#define NCP     28        // chunk-pairs per row (2 * CDIM per block)
#define G       32        // segments per block
#define NGRP    (NB / G)  // 64 groups

// ---------------------------------------------------------------------------
// Fully fused kernel: embedding gather + segment mean + projection.
// grid = (28 chunk-pairs, 64 segment-groups), block = 256 threads (8 warps).
//
// Per block:
//   for cp in {0,1}:  chunk = blockIdx.x*2 + cp   (64 dims each)
//     - stage Ws[64][128] (32 KB) from proj_w
//     - warp w gathers segments {w, w+8, w+16, w+24}: 32 token rows x 64 dims
//       (float2 per lane, 256 B coalesced per token row), mean -> smem
//     - matvec: thread (n-pair, 8-seg group) accumulates acc[8][2] registers
//   epilogue: atomicAdd into out (+bias from chunk-pair 0)
//
// All compute (FMA ~52us, crossbar ~65us, atomics ~26us chip-wide) hides
// under the 939 MB HBM gather wall (~125us).
// ---------------------------------------------------------------------------
__global__ __launch_bounds__(256, 2) void fused_gather_proj_kernel(
    const int*   __restrict__ flat_idx,
    const int*   __restrict__ lens,
    const float* __restrict__ embed,
    const float* __restrict__ W,
    const float* __restrict__ bias,
    float*       __restrict__ out)
{
    __shared__ float Ws[CDIM][D_ENC];      // 32 KB, reloaded per chunk pass
    __shared__ float means[G][CDIM];       // 8 KB
    __shared__ int   idx_s[G * SEG];       // 4 KB

    const int grp  = blockIdx.y;
    const int t    = threadIdx.x;
    const int w    = t >> 5;
    const int lane = t & 31;

    // output-tile mapping for the matvec/epilogue
    const int np = t & 63;    // n-pair index: n = np*2, np*2+1
    const int sg = t >> 6;    // 0..3 -> segments sg*8 .. sg*8+7

    // Load the group's 1024 token indices (contiguous, seg-major)
    {
        const int base = grp * (G * SEG);
        #pragma unroll
        for (int i = 0; i < (G * SEG) / 256; i++)
            idx_s[t + i * 256] = flat_idx[base + t + i * 256];
    }

    float acc[8][2];
    #pragma unroll
    for (int j = 0; j < 8; j++) { acc[j][0] = 0.f; acc[j][1] = 0.f; }

    #pragma unroll 1
    for (int cp = 0; cp < 2; cp++) {
        const int chunk = blockIdx.x * 2 + cp;

        __syncthreads();  // cp0: idx ready; cp1: previous matvec done

        // Stage W slice: Ws[d][n] = W[(chunk*CDIM + d) * D_ENC + n]
        {
            const float* Wc = W + (size_t)chunk * CDIM * D_ENC;
            #pragma unroll
            for (int i = 0; i < (CDIM * D_ENC) / (256 * 4); i++) {  // 8 iters
                const int e = (t + i * 256) * 4;
                *reinterpret_cast<float4*>(&Ws[0][0] + e) =
                    *reinterpret_cast<const float4*>(Wc + e);
            }
        }

        // Gather + mean: warp w handles segments w, w+8, w+16, w+24
        {
            const int doff = chunk * CDIM + lane * 2;  // float2 per lane
            #pragma unroll 1
            for (int r = 0; r < 4; r++) {
                const int s = w + r * 8;
                float ax = 0.f, ay = 0.f;
                #pragma unroll
                for (int tok = 0; tok < SEG; tok++) {
                    const int idx = idx_s[s * SEG + tok];
                    const float2 v = __ldg(reinterpret_cast<const float2*>(
                        embed + (size_t)idx * D_MODEL + doff));
                    ax += v.x; ay += v.y;
                }
                const float inv = 1.0f / (float)__ldg(&lens[grp * G + s]);
                *reinterpret_cast<float2*>(&means[s][lane * 2]) =
                    make_float2(ax * inv, ay * inv);
            }
        }
        __syncthreads();  // Ws + means ready

        // Matvec accumulate: acc[j][0..1] += means[sg*8+j][d] * Ws[d][np*2..+1]
        #pragma unroll 8
        for (int d = 0; d < CDIM; d++) {
            const float2 wv = *reinterpret_cast<const float2*>(&Ws[d][np * 2]);
            #pragma unroll
            for (int j = 0; j < 8; j++) {
                const float m = means[sg * 8 + j][d];  // warp broadcast
                acc[j][0] = fmaf(m, wv.x, acc[j][0]);
                acc[j][1] = fmaf(m, wv.y, acc[j][1]);
            }
        }
    }

    // Epilogue: atomic accumulate (28 chunk-pair blocks per output element).
    // Chunk-pair 0 also adds the bias.
    const bool add_bias = (blockIdx.x == 0);
    const int  n  = np * 2;
    const float b0 = add_bias ? bias[n]     : 0.f;
    const float b1 = add_bias ? bias[n + 1] : 0.f;
    #pragma unroll
    for (int j = 0; j < 8; j++) {
        const int s = grp * G + sg * 8 + j;
        atomicAdd(&out[(size_t)s * D_ENC + n],     acc[j][0] + b0);
        atomicAdd(&out[(size_t)s * D_ENC + n + 1], acc[j][1] + b1);
    }
}

// ---------------------------------------------------------------------------
// Launch.  Inputs (metadata order):
//   0: flat_idx int32 [65536]   1: seg int32 [65536]   2: lens int32 [2048]
//   3: embed_weight f32 [50000*3584]  4: proj_w f32 [3584*128]  5: proj_b f32 [128]
// Output: f32 [2048*128]
// ---------------------------------------------------------------------------
extern "C" void kernel_launch(void* const* d_in, const int* in_sizes, int n_in,
                              void* d_out, int out_size)
{
    const int*   flat_idx = (const int*)d_in[0];
    const int*   lens     = (const int*)d_in[2];
    const float* embed    = (const float*)d_in[3];
    const float* proj_w   = (const float*)d_in[4];
    const float* proj_b   = (const float*)d_in[5];
    float*       out      = (float*)d_out;

    // zero output (atomics accumulate; bias added by chunk-pair 0)
    cudaMemsetAsync(out, 0, (size_t)NB * D_ENC * sizeof(float));

    fused_gather_proj_kernel<<<dim3(NCP, NGRP), 256>>>(
        flat_idx, lens, embed, proj_w, proj_b, out);
}